// round 1
// baseline (speedup 1.0000x reference)
#include <cuda_runtime.h>
#include <math.h>

// Problem constants
#define NB 64
#define NS 400
#define NV 50000
#define NE 128
#define NH 512
#define NM 512
#define NOOV 20
#define NVO (NV + NOOV)

// Output layout (flattened concatenation of reference outputs)
#define SZ_FD   (NB * NVO)          // 3201280
#define OFF_H   (SZ_FD)             // h_next [1,B,H]
#define OFF_WC  (OFF_H  + NB * NH)  // word_context [B,M]
#define OFF_AT  (OFF_WC + NB * NM)  // attn [B,S]
#define OFF_PG  (OFF_AT + NB * NS)  // p_gen [B,1]
#define OFF_CV  (OFF_PG + NB)       // coverage_next [B,S]
#define TOTAL_OUT (OFF_CV + NB * NS)

// Scratch (device globals: no allocation allowed)
__device__ float g_h1[NB * NH];
__device__ float g_dec[NB * NH];
__device__ float g_scores[NB * NS];
__device__ float g_attn[NB * NS];
__device__ float g_wc[NB * NM];
__device__ float g_hid[NB * NH];
__device__ float g_pgen[NB];
__device__ float g_logits[(size_t)NB * NV];

__device__ __forceinline__ float sigmoidf_(float x) { return 1.0f / (1.0f + expf(-x)); }

// ---------------------------------------------------------------------------
// K1: embedding gather + GRU step + dec_feat ; also zeros score scratch
// grid = NB blocks, 256 threads
// ---------------------------------------------------------------------------
__global__ void k1_gru(const int* __restrict__ y, const float* __restrict__ h0g,
                       const float* __restrict__ emb_W,
                       const float* __restrict__ Wih, const float* __restrict__ Whh,
                       const float* __restrict__ bih, const float* __restrict__ bhh,
                       const float* __restrict__ Wd, const float* __restrict__ bd,
                       float* __restrict__ out, int out_size)
{
    __shared__ float emb[NE];
    __shared__ float h0s[NH];
    __shared__ float h1s[NH];
    int b = blockIdx.x, tid = threadIdx.x;
    int yb = y[b];
    for (int i = tid; i < NE; i += blockDim.x) emb[i] = emb_W[(size_t)yb * NE + i];
    for (int i = tid; i < NH; i += blockDim.x) h0s[i] = h0g[b * NH + i];
    for (int i = tid; i < NS; i += blockDim.x) g_scores[b * NS + i] = 0.0f;
    __syncthreads();

    for (int j = tid; j < NH; j += blockDim.x) {
        float gir = bih[j], giz = bih[j + NH], gin = bih[j + 2 * NH];
        const float4* wr = (const float4*)(Wih + (size_t)j * NE);
        const float4* wz = (const float4*)(Wih + (size_t)(j + NH) * NE);
        const float4* wn = (const float4*)(Wih + (size_t)(j + 2 * NH) * NE);
        const float4* es = (const float4*)emb;
#pragma unroll 8
        for (int k = 0; k < NE / 4; k++) {
            float4 e = es[k];
            float4 a = wr[k]; gir += e.x * a.x + e.y * a.y + e.z * a.z + e.w * a.w;
            float4 c = wz[k]; giz += e.x * c.x + e.y * c.y + e.z * c.z + e.w * c.w;
            float4 d = wn[k]; gin += e.x * d.x + e.y * d.y + e.z * d.z + e.w * d.w;
        }
        float ghr = bhh[j], ghz = bhh[j + NH], ghn = bhh[j + 2 * NH];
        const float4* hr = (const float4*)(Whh + (size_t)j * NH);
        const float4* hz = (const float4*)(Whh + (size_t)(j + NH) * NH);
        const float4* hn = (const float4*)(Whh + (size_t)(j + 2 * NH) * NH);
        const float4* hs = (const float4*)h0s;
#pragma unroll 8
        for (int k = 0; k < NH / 4; k++) {
            float4 e = hs[k];
            float4 a = hr[k]; ghr += e.x * a.x + e.y * a.y + e.z * a.z + e.w * a.w;
            float4 c = hz[k]; ghz += e.x * c.x + e.y * c.y + e.z * c.z + e.w * c.w;
            float4 d = hn[k]; ghn += e.x * d.x + e.y * d.y + e.z * d.z + e.w * d.w;
        }
        float r = sigmoidf_(gir + ghr);
        float z = sigmoidf_(giz + ghz);
        float n = tanhf(gin + r * ghn);
        float hv = (1.0f - z) * n + z * h0s[j];
        h1s[j] = hv;
        g_h1[b * NH + j] = hv;
    }
    __syncthreads();

    // dec_feat = h1 @ Wd^T + bd
    for (int j = tid; j < NH; j += blockDim.x) {
        float acc = bd[j];
        const float4* w = (const float4*)(Wd + (size_t)j * NH);
        const float4* hs = (const float4*)h1s;
#pragma unroll 8
        for (int k = 0; k < NH / 4; k++) {
            float4 ww = w[k]; float4 hh = hs[k];
            acc += ww.x * hh.x + ww.y * hh.y + ww.z * hh.z + ww.w * hh.w;
        }
        g_dec[b * NH + j] = acc;
    }
    if (out_size >= TOTAL_OUT) {
        for (int j = tid; j < NH; j += blockDim.x) out[OFF_H + b * NH + j] = h1s[j];
    }
}

// ---------------------------------------------------------------------------
// K2: enc_feat GEMM fused with attention score epilogue.
// C[25600, 512] = MB[25600,512] @ Wm^T ; score[row] += sum_h v[h]*tanh(C+dec+cov*Wc)
// Tiles: BM=128, BN=128, BK=16; 256 threads; 8x8 microtile (split 2x2 of 4x4).
// grid = (25600/128=200, 512/128=4)
// ---------------------------------------------------------------------------
#define BM2 128
#define BN2 128
#define BK2 16

__global__ __launch_bounds__(256, 2)
void k2_scores(const float* __restrict__ MB, const float* __restrict__ Wm,
               const float* __restrict__ Wc, const float* __restrict__ av,
               const float* __restrict__ cov)
{
    __shared__ float As[BK2][BM2];
    __shared__ float Bs[BK2][BN2];
    __shared__ float ssum[BM2];

    int tid = threadIdx.x;
    int tx = tid & 15, ty = tid >> 4;
    int mBase = blockIdx.x * BM2;
    int nBase = blockIdx.y * BN2;

    float acc[8][8];
#pragma unroll
    for (int i = 0; i < 8; i++)
#pragma unroll
        for (int j = 0; j < 8; j++) acc[i][j] = 0.0f;

    for (int k0 = 0; k0 < NM; k0 += BK2) {
#pragma unroll
        for (int it = 0; it < 2; it++) {
            int idx = tid + it * 256;
            int r = idx >> 2, c4 = idx & 3;
            float4 a4 = *(const float4*)&MB[(size_t)(mBase + r) * NM + k0 + c4 * 4];
            As[c4 * 4 + 0][r] = a4.x; As[c4 * 4 + 1][r] = a4.y;
            As[c4 * 4 + 2][r] = a4.z; As[c4 * 4 + 3][r] = a4.w;
            float4 b4 = *(const float4*)&Wm[(size_t)(nBase + r) * NM + k0 + c4 * 4];
            Bs[c4 * 4 + 0][r] = b4.x; Bs[c4 * 4 + 1][r] = b4.y;
            Bs[c4 * 4 + 2][r] = b4.z; Bs[c4 * 4 + 3][r] = b4.w;
        }
        __syncthreads();
#pragma unroll
        for (int kk = 0; kk < BK2; kk++) {
            float4 a0 = *(const float4*)&As[kk][ty * 4];
            float4 a1 = *(const float4*)&As[kk][64 + ty * 4];
            float4 b0 = *(const float4*)&Bs[kk][tx * 4];
            float4 b1 = *(const float4*)&Bs[kk][64 + tx * 4];
            float ar[8] = {a0.x, a0.y, a0.z, a0.w, a1.x, a1.y, a1.z, a1.w};
            float br[8] = {b0.x, b0.y, b0.z, b0.w, b1.x, b1.y, b1.z, b1.w};
#pragma unroll
            for (int i = 0; i < 8; i++)
#pragma unroll
                for (int j = 0; j < 8; j++) acc[i][j] += ar[i] * br[j];
        }
        __syncthreads();
    }

    // epilogue: partial score reduction over this block's 128 h-columns
    for (int i = tid; i < BM2; i += 256) ssum[i] = 0.0f;
    __syncthreads();

#pragma unroll
    for (int i = 0; i < 8; i++) {
        int r = (i < 4) ? (ty * 4 + i) : (64 + ty * 4 + i - 4);
        int gr = mBase + r;
        int b = gr / NS;
        int s = gr - b * NS;
        float cv = cov[b * NS + s];
        float partial = 0.0f;
#pragma unroll
        for (int j = 0; j < 8; j++) {
            int hc = nBase + ((j < 4) ? (tx * 4 + j) : (64 + tx * 4 + j - 4));
            float x = acc[i][j] + g_dec[b * NH + hc] + cv * Wc[hc];
            partial += av[hc] * tanhf(x);
        }
        atomicAdd(&ssum[r], partial);
    }
    __syncthreads();
    for (int r = tid; r < BM2; r += 256) {
        atomicAdd(&g_scores[mBase + r], ssum[r]);
    }
}

// ---------------------------------------------------------------------------
// K3: masked softmax, coverage, word_context, p_gen, vd1 hidden
// grid = NB blocks, 512 threads
// ---------------------------------------------------------------------------
__global__ void k3_attn(const float* __restrict__ MB, const float* __restrict__ mask,
                        const float* __restrict__ cov,
                        const int* __restrict__ y, const float* __restrict__ emb_W,
                        const float* __restrict__ pgen_W, const float* __restrict__ pgen_b,
                        const float* __restrict__ vd1_W, const float* __restrict__ vd1_b,
                        float* __restrict__ out, int out_size)
{
    int b = blockIdx.x, tid = threadIdx.x;
    bool full = (out_size >= TOTAL_OUT);
    __shared__ float sc[NS];
    __shared__ float att[NS];
    __shared__ float red[512];
    __shared__ float wcs[NM];
    __shared__ float h1s[NH];

    for (int i = tid; i < NS; i += 512) {
        float m = mask[b * NS + i];
        sc[i] = (m > 0.0f) ? g_scores[b * NS + i] : -1e9f;
    }
    for (int i = tid; i < NH; i += 512) h1s[i] = g_h1[b * NH + i];
    __syncthreads();

    // max
    float mx = -1e30f;
    for (int i = tid; i < NS; i += 512) mx = fmaxf(mx, sc[i]);
    red[tid] = mx; __syncthreads();
    for (int o = 256; o > 0; o >>= 1) { if (tid < o) red[tid] = fmaxf(red[tid], red[tid + o]); __syncthreads(); }
    mx = red[0]; __syncthreads();

    // exp & sum
    float sm = 0.0f;
    for (int i = tid; i < NS; i += 512) { float e = expf(sc[i] - mx); sc[i] = e; sm += e; }
    red[tid] = sm; __syncthreads();
    for (int o = 256; o > 0; o >>= 1) { if (tid < o) red[tid] += red[tid + o]; __syncthreads(); }
    sm = red[0]; __syncthreads();

    // attn = softmax * mask, renormalize
    float s2 = 0.0f;
    for (int i = tid; i < NS; i += 512) {
        float m = mask[b * NS + i];
        float a = sc[i] / sm * m;
        att[i] = a; s2 += a;
    }
    red[tid] = s2; __syncthreads();
    for (int o = 256; o > 0; o >>= 1) { if (tid < o) red[tid] += red[tid + o]; __syncthreads(); }
    s2 = red[0]; __syncthreads();
    float inv = 1.0f / (s2 + 1e-10f);
    for (int i = tid; i < NS; i += 512) {
        float a = att[i] * inv;
        att[i] = a;
        g_attn[b * NS + i] = a;
        if (full) {
            out[OFF_AT + b * NS + i] = a;
            out[OFF_CV + b * NS + i] = cov[b * NS + i] + a;
        }
    }
    __syncthreads();

    // word_context: thread tid handles memory dim m=tid (512 threads == NM)
    {
        float a0 = 0.0f;
        const float* mbb = MB + (size_t)b * NS * NM + tid;
#pragma unroll 4
        for (int s = 0; s < NS; s++) a0 += att[s] * mbb[(size_t)s * NM];
        wcs[tid] = a0;
        g_wc[b * NM + tid] = a0;
        if (full) out[OFF_WC + b * NM + tid] = a0;
    }
    __syncthreads();

    // p_gen = sigmoid(pgen_W . [wc, h1, y_emb] + b)
    int yb = y[b];
    float ps = 0.0f;
    for (int i = tid; i < NM + NH + NE; i += 512) {
        float xv = (i < NM) ? wcs[i]
                 : (i < NM + NH) ? h1s[i - NM]
                 : emb_W[(size_t)yb * NE + (i - NM - NH)];
        ps += pgen_W[i] * xv;
    }
    red[tid] = ps; __syncthreads();
    for (int o = 256; o > 0; o >>= 1) { if (tid < o) red[tid] += red[tid + o]; __syncthreads(); }
    float p = sigmoidf_(red[0] + pgen_b[0]);
    if (tid == 0) {
        g_pgen[b] = p;
        if (full) out[OFF_PG + b] = p;
    }

    // hid = vd1_W @ [wc, h1] + vd1_b
    for (int j = tid; j < NH; j += 512) {
        float a0 = vd1_b[j];
        const float4* w = (const float4*)(vd1_W + (size_t)j * (NM + NH));
        const float4* xw = (const float4*)wcs;
        const float4* xh = (const float4*)h1s;
#pragma unroll 8
        for (int k = 0; k < NM / 4; k++) {
            float4 ww = w[k]; float4 xx = xw[k];
            a0 += ww.x * xx.x + ww.y * xx.y + ww.z * xx.z + ww.w * xx.w;
        }
        const float4* w2 = w + NM / 4;
#pragma unroll 8
        for (int k = 0; k < NH / 4; k++) {
            float4 ww = w2[k]; float4 xx = xh[k];
            a0 += ww.x * xx.x + ww.y * xx.y + ww.z * xx.z + ww.w * xx.w;
        }
        g_hid[b * NH + j] = a0;
    }
}

// ---------------------------------------------------------------------------
// K4a: vocab logits GEMM: C[64, 50000] = hid[64,512] @ vd2_W^T + b
// Tiles BM=64(all b), BN=64, BK=16; 256 threads, 4x4 microtile. grid=782
// ---------------------------------------------------------------------------
__global__ __launch_bounds__(256)
void k4a_logits(const float* __restrict__ W2, const float* __restrict__ b2)
{
    __shared__ float As[16][64];
    __shared__ float Bs[16][64];
    int tid = threadIdx.x;
    int tx = tid & 15, ty = tid >> 4;
    int vBase = blockIdx.x * 64;

    float acc[4][4];
#pragma unroll
    for (int i = 0; i < 4; i++)
#pragma unroll
        for (int j = 0; j < 4; j++) acc[i][j] = 0.0f;

    int r = tid >> 2, c4 = tid & 3;
    int vr = vBase + r;
    bool vok = (vr < NV);

    for (int k0 = 0; k0 < NH; k0 += 16) {
        float4 a4 = *(const float4*)&g_hid[(size_t)r * NH + k0 + c4 * 4];
        As[c4 * 4 + 0][r] = a4.x; As[c4 * 4 + 1][r] = a4.y;
        As[c4 * 4 + 2][r] = a4.z; As[c4 * 4 + 3][r] = a4.w;
        float4 b4 = vok ? *(const float4*)&W2[(size_t)vr * NH + k0 + c4 * 4]
                        : make_float4(0.f, 0.f, 0.f, 0.f);
        Bs[c4 * 4 + 0][r] = b4.x; Bs[c4 * 4 + 1][r] = b4.y;
        Bs[c4 * 4 + 2][r] = b4.z; Bs[c4 * 4 + 3][r] = b4.w;
        __syncthreads();
#pragma unroll
        for (int kk = 0; kk < 16; kk++) {
            float4 a = *(const float4*)&As[kk][ty * 4];
            float4 bb = *(const float4*)&Bs[kk][tx * 4];
            float ar[4] = {a.x, a.y, a.z, a.w};
            float br[4] = {bb.x, bb.y, bb.z, bb.w};
#pragma unroll
            for (int i = 0; i < 4; i++)
#pragma unroll
                for (int j = 0; j < 4; j++) acc[i][j] += ar[i] * br[j];
        }
        __syncthreads();
    }
#pragma unroll
    for (int i = 0; i < 4; i++) {
        int bb = ty * 4 + i;
#pragma unroll
        for (int j = 0; j < 4; j++) {
            int v = vBase + tx * 4 + j;
            if (v < NV) g_logits[(size_t)bb * NV + v] = acc[i][j] + b2[v];
        }
    }
}

// ---------------------------------------------------------------------------
// K4b: vocab softmax, pointer-generator merge, OOV scatter. grid=NB, 1024 thr
// ---------------------------------------------------------------------------
__global__ void k4b_final(const int* __restrict__ src_oov, float* __restrict__ out)
{
    int b = blockIdx.x, tid = threadIdx.x;
    __shared__ float red[1024];
    const float* lg = &g_logits[(size_t)b * NV];

    float mx = -1e30f;
    for (int v = tid; v < NV; v += 1024) mx = fmaxf(mx, lg[v]);
    red[tid] = mx; __syncthreads();
    for (int o = 512; o > 0; o >>= 1) { if (tid < o) red[tid] = fmaxf(red[tid], red[tid + o]); __syncthreads(); }
    mx = red[0]; __syncthreads();

    float sm = 0.0f;
    for (int v = tid; v < NV; v += 1024) sm += expf(lg[v] - mx);
    red[tid] = sm; __syncthreads();
    for (int o = 512; o > 0; o >>= 1) { if (tid < o) red[tid] += red[tid + o]; __syncthreads(); }
    sm = red[0]; __syncthreads();

    float p = g_pgen[b];
    float scale = p / sm;
    float* orow = out + (size_t)b * NVO;
    for (int v = tid; v < NV; v += 1024) orow[v] = expf(lg[v] - mx) * scale;
    for (int v = NV + tid; v < NVO; v += 1024) orow[v] = 0.0f;
    __syncthreads();

    float q = 1.0f - p;
    for (int s = tid; s < NS; s += 1024) {
        atomicAdd(&orow[src_oov[b * NS + s]], q * g_attn[b * NS + s]);
    }
}

// ---------------------------------------------------------------------------
extern "C" void kernel_launch(void* const* d_in, const int* in_sizes, int n_in,
                              void* d_out, int out_size)
{
    // Input order per setup_inputs(); max_num_oovs scalar may or may not be
    // materialized as an input — detect via n_in.
    int sh = (n_in >= 23) ? 1 : 0;
    const int*   y        = (const int*)  d_in[0];
    const float* h0g      = (const float*)d_in[1];
    const float* MB       = (const float*)d_in[2];
    const float* mask     = (const float*)d_in[3];
    const int*   src_oov  = (const int*)  d_in[4 + sh];
    const float* cov      = (const float*)d_in[5 + sh];
    const float* emb_W    = (const float*)d_in[6 + sh];
    const float* Wih      = (const float*)d_in[7 + sh];
    const float* Whh      = (const float*)d_in[8 + sh];
    const float* bih      = (const float*)d_in[9 + sh];
    const float* bhh      = (const float*)d_in[10 + sh];
    const float* Wm       = (const float*)d_in[11 + sh];
    const float* Wd       = (const float*)d_in[12 + sh];
    const float* bd       = (const float*)d_in[13 + sh];
    const float* Wc       = (const float*)d_in[14 + sh];
    const float* av       = (const float*)d_in[15 + sh];
    const float* pgen_W   = (const float*)d_in[16 + sh];
    const float* pgen_b   = (const float*)d_in[17 + sh];
    const float* vd1_W    = (const float*)d_in[18 + sh];
    const float* vd1_b    = (const float*)d_in[19 + sh];
    const float* W2       = (const float*)d_in[20 + sh];
    const float* b2       = (const float*)d_in[21 + sh];
    float* out = (float*)d_out;

    k1_gru<<<NB, 256>>>(y, h0g, emb_W, Wih, Whh, bih, bhh, Wd, bd, out, out_size);

    dim3 g2((NB * NS) / BM2, NM / BN2);   // (200, 4)
    k2_scores<<<g2, 256>>>(MB, Wm, Wc, av, cov);

    k3_attn<<<NB, 512>>>(MB, mask, cov, y, emb_W, pgen_W, pgen_b, vd1_W, vd1_b, out, out_size);

    k4a_logits<<<(NV + 63) / 64, 256>>>(W2, b2);

    k4b_final<<<NB, 1024>>>(src_oov, out);
}

// round 2
// speedup vs baseline: 1.4194x; 1.4194x over previous
#include <cuda_runtime.h>
#include <math.h>

// Problem constants
#define NB 64
#define NS 400
#define NV 50000
#define NE 128
#define NH 512
#define NM 512
#define NOOV 20
#define NVO (NV + NOOV)

// Output layout (flattened concatenation of reference outputs)
#define SZ_FD   (NB * NVO)
#define OFF_H   (SZ_FD)
#define OFF_WC  (OFF_H  + NB * NH)
#define OFF_AT  (OFF_WC + NB * NM)
#define OFF_PG  (OFF_AT + NB * NS)
#define OFF_CV  (OFF_PG + NB)
#define TOTAL_OUT (OFF_CV + NB * NS)

// Scratch (device globals: no allocation allowed)
__device__ float g_h1[NB * NH];
__device__ float g_dec[NB * NH];
__device__ float g_scores[NB * NS];
__device__ float g_attn[NB * NS];
__device__ float g_wc[NB * NM];
__device__ float g_hid[NB * NH];
__device__ float g_pgen[NB];
__device__ float g_logits[(size_t)NB * NV];

__device__ __forceinline__ float sigmoidf_(float x) { return 1.0f / (1.0f + expf(-x)); }

__device__ __forceinline__ unsigned f2tf(float x) {
    unsigned r; asm("cvt.rna.tf32.f32 %0, %1;" : "=r"(r) : "f"(x)); return r;
}
__device__ __forceinline__ void mma_tf32(float c[4], unsigned a0, unsigned a1,
                                         unsigned a2, unsigned a3,
                                         unsigned b0, unsigned b1) {
    asm volatile("mma.sync.aligned.m16n8k8.row.col.f32.tf32.tf32.f32 "
                 "{%0,%1,%2,%3}, {%4,%5,%6,%7}, {%8,%9}, {%0,%1,%2,%3};"
                 : "+f"(c[0]), "+f"(c[1]), "+f"(c[2]), "+f"(c[3])
                 : "r"(a0), "r"(a1), "r"(a2), "r"(a3), "r"(b0), "r"(b1));
}

// ---------------------------------------------------------------------------
// K1: embedding gather + GRU step + dec_feat ; also zeros score scratch
// ---------------------------------------------------------------------------
__global__ void k1_gru(const int* __restrict__ y, const float* __restrict__ h0g,
                       const float* __restrict__ emb_W,
                       const float* __restrict__ Wih, const float* __restrict__ Whh,
                       const float* __restrict__ bih, const float* __restrict__ bhh,
                       const float* __restrict__ Wd, const float* __restrict__ bd,
                       float* __restrict__ out, int out_size)
{
    __shared__ float emb[NE];
    __shared__ float h0s[NH];
    __shared__ float h1s[NH];
    int b = blockIdx.x, tid = threadIdx.x;
    int yb = y[b];
    for (int i = tid; i < NE; i += blockDim.x) emb[i] = emb_W[(size_t)yb * NE + i];
    for (int i = tid; i < NH; i += blockDim.x) h0s[i] = h0g[b * NH + i];
    for (int i = tid; i < NS; i += blockDim.x) g_scores[b * NS + i] = 0.0f;
    __syncthreads();

    for (int j = tid; j < NH; j += blockDim.x) {
        float gir = bih[j], giz = bih[j + NH], gin = bih[j + 2 * NH];
        const float4* wr = (const float4*)(Wih + (size_t)j * NE);
        const float4* wz = (const float4*)(Wih + (size_t)(j + NH) * NE);
        const float4* wn = (const float4*)(Wih + (size_t)(j + 2 * NH) * NE);
        const float4* es = (const float4*)emb;
#pragma unroll 8
        for (int k = 0; k < NE / 4; k++) {
            float4 e = es[k];
            float4 a = wr[k]; gir += e.x * a.x + e.y * a.y + e.z * a.z + e.w * a.w;
            float4 c = wz[k]; giz += e.x * c.x + e.y * c.y + e.z * c.z + e.w * c.w;
            float4 d = wn[k]; gin += e.x * d.x + e.y * d.y + e.z * d.z + e.w * d.w;
        }
        float ghr = bhh[j], ghz = bhh[j + NH], ghn = bhh[j + 2 * NH];
        const float4* hr = (const float4*)(Whh + (size_t)j * NH);
        const float4* hz = (const float4*)(Whh + (size_t)(j + NH) * NH);
        const float4* hn = (const float4*)(Whh + (size_t)(j + 2 * NH) * NH);
        const float4* hs = (const float4*)h0s;
#pragma unroll 8
        for (int k = 0; k < NH / 4; k++) {
            float4 e = hs[k];
            float4 a = hr[k]; ghr += e.x * a.x + e.y * a.y + e.z * a.z + e.w * a.w;
            float4 c = hz[k]; ghz += e.x * c.x + e.y * c.y + e.z * c.z + e.w * c.w;
            float4 d = hn[k]; ghn += e.x * d.x + e.y * d.y + e.z * d.z + e.w * d.w;
        }
        float r = sigmoidf_(gir + ghr);
        float z = sigmoidf_(giz + ghz);
        float n = tanhf(gin + r * ghn);
        float hv = (1.0f - z) * n + z * h0s[j];
        h1s[j] = hv;
        g_h1[b * NH + j] = hv;
    }
    __syncthreads();

    for (int j = tid; j < NH; j += blockDim.x) {
        float acc = bd[j];
        const float4* w = (const float4*)(Wd + (size_t)j * NH);
        const float4* hs = (const float4*)h1s;
#pragma unroll 8
        for (int k = 0; k < NH / 4; k++) {
            float4 ww = w[k]; float4 hh = hs[k];
            acc += ww.x * hh.x + ww.y * hh.y + ww.z * hh.z + ww.w * hh.w;
        }
        g_dec[b * NH + j] = acc;
    }
    if (out_size >= TOTAL_OUT) {
        for (int j = tid; j < NH; j += blockDim.x) out[OFF_H + b * NH + j] = h1s[j];
    }
}

// ---------------------------------------------------------------------------
// K2: enc_feat GEMM (tf32 mma) fused with attention score epilogue.
// C[25600,512] = MB @ Wm^T ; score[row] += sum_h v[h]*tanh(C+dec+cov*Wc)
// BM=128, BN=128, BK=16; 256 thr = 8 warps (4m x 2n); warp tile 32x64.
// grid = (200, 4)
// ---------------------------------------------------------------------------
#define LDK 20   // smem row stride (16 + 4 pad) -> conflict-free frag loads

__global__ __launch_bounds__(256, 1)
void k2_scores(const float* __restrict__ MB, const float* __restrict__ Wm,
               const float* __restrict__ Wc, const float* __restrict__ av,
               const float* __restrict__ cov)
{
    __shared__ unsigned As[128 * LDK];
    __shared__ unsigned Bs[128 * LDK];
    __shared__ float ssum[128];

    int tid = threadIdx.x;
    int wid = tid >> 5, lane = tid & 31;
    int g = lane >> 2, tig = lane & 3;
    int warp_m = wid & 3, warp_n = wid >> 2;
    int mBase = blockIdx.x * 128;
    int nBase = blockIdx.y * 128;

    float acc[2][8][4];
#pragma unroll
    for (int i = 0; i < 2; i++)
#pragma unroll
        for (int j = 0; j < 8; j++)
#pragma unroll
            for (int q = 0; q < 4; q++) acc[i][j][q] = 0.0f;

    int lr = tid >> 2, lc = (tid & 3) * 4;

    for (int k0 = 0; k0 < NM; k0 += 16) {
#pragma unroll
        for (int it = 0; it < 2; it++) {
            int r = lr + it * 64;
            float4 a4 = *(const float4*)&MB[(size_t)(mBase + r) * NM + k0 + lc];
            uint4 av4 = make_uint4(f2tf(a4.x), f2tf(a4.y), f2tf(a4.z), f2tf(a4.w));
            *(uint4*)&As[r * LDK + lc] = av4;
            float4 b4 = *(const float4*)&Wm[(size_t)(nBase + r) * NM + k0 + lc];
            uint4 bv4 = make_uint4(f2tf(b4.x), f2tf(b4.y), f2tf(b4.z), f2tf(b4.w));
            *(uint4*)&Bs[r * LDK + lc] = bv4;
        }
        __syncthreads();

#pragma unroll
        for (int ks = 0; ks < 2; ks++) {
            int kb = ks * 8;
            unsigned bf[8][2];
#pragma unroll
            for (int j = 0; j < 8; j++) {
                int col = warp_n * 64 + j * 8 + g;
                bf[j][0] = Bs[col * LDK + kb + tig];
                bf[j][1] = Bs[col * LDK + kb + tig + 4];
            }
#pragma unroll
            for (int i = 0; i < 2; i++) {
                int row = warp_m * 32 + i * 16 + g;
                unsigned a0 = As[row * LDK + kb + tig];
                unsigned a1 = As[(row + 8) * LDK + kb + tig];
                unsigned a2 = As[row * LDK + kb + tig + 4];
                unsigned a3 = As[(row + 8) * LDK + kb + tig + 4];
#pragma unroll
                for (int j = 0; j < 8; j++)
                    mma_tf32(acc[i][j], a0, a1, a2, a3, bf[j][0], bf[j][1]);
            }
        }
        __syncthreads();
    }

    // epilogue: partial score reduction over this block's 128 h-columns
    for (int i = tid; i < 128; i += 256) ssum[i] = 0.0f;
    __syncthreads();

#pragma unroll
    for (int i = 0; i < 2; i++) {
#pragma unroll
        for (int h = 0; h < 2; h++) {
            int r = warp_m * 32 + i * 16 + g + h * 8;
            int gr = mBase + r;
            int b = gr / NS;
            int s = gr - b * NS;
            float cv = cov[b * NS + s];
            float partial = 0.0f;
#pragma unroll
            for (int j = 0; j < 8; j++) {
                int hc = nBase + warp_n * 64 + j * 8 + 2 * tig;
                float c0 = acc[i][j][h * 2 + 0];
                float c1 = acc[i][j][h * 2 + 1];
                partial += av[hc]     * tanhf(c0 + g_dec[b * NH + hc]     + cv * Wc[hc]);
                partial += av[hc + 1] * tanhf(c1 + g_dec[b * NH + hc + 1] + cv * Wc[hc + 1]);
            }
            atomicAdd(&ssum[r], partial);
        }
    }
    __syncthreads();
    for (int r = tid; r < 128; r += 256) {
        atomicAdd(&g_scores[mBase + r], ssum[r]);
    }
}

// ---------------------------------------------------------------------------
// K3: masked softmax, coverage, word_context, p_gen, vd1 hidden
// ---------------------------------------------------------------------------
__global__ void k3_attn(const float* __restrict__ MB, const float* __restrict__ mask,
                        const float* __restrict__ cov,
                        const int* __restrict__ y, const float* __restrict__ emb_W,
                        const float* __restrict__ pgen_W, const float* __restrict__ pgen_b,
                        const float* __restrict__ vd1_W, const float* __restrict__ vd1_b,
                        float* __restrict__ out, int out_size)
{
    int b = blockIdx.x, tid = threadIdx.x;
    bool full = (out_size >= TOTAL_OUT);
    __shared__ float sc[NS];
    __shared__ float att[NS];
    __shared__ float red[512];
    __shared__ float wcs[NM];
    __shared__ float h1s[NH];

    for (int i = tid; i < NS; i += 512) {
        float m = mask[b * NS + i];
        sc[i] = (m > 0.0f) ? g_scores[b * NS + i] : -1e9f;
    }
    for (int i = tid; i < NH; i += 512) h1s[i] = g_h1[b * NH + i];
    __syncthreads();

    float mx = -1e30f;
    for (int i = tid; i < NS; i += 512) mx = fmaxf(mx, sc[i]);
    red[tid] = mx; __syncthreads();
    for (int o = 256; o > 0; o >>= 1) { if (tid < o) red[tid] = fmaxf(red[tid], red[tid + o]); __syncthreads(); }
    mx = red[0]; __syncthreads();

    float sm = 0.0f;
    for (int i = tid; i < NS; i += 512) { float e = expf(sc[i] - mx); sc[i] = e; sm += e; }
    red[tid] = sm; __syncthreads();
    for (int o = 256; o > 0; o >>= 1) { if (tid < o) red[tid] += red[tid + o]; __syncthreads(); }
    sm = red[0]; __syncthreads();

    float s2 = 0.0f;
    for (int i = tid; i < NS; i += 512) {
        float m = mask[b * NS + i];
        float a = sc[i] / sm * m;
        att[i] = a; s2 += a;
    }
    red[tid] = s2; __syncthreads();
    for (int o = 256; o > 0; o >>= 1) { if (tid < o) red[tid] += red[tid + o]; __syncthreads(); }
    s2 = red[0]; __syncthreads();
    float inv = 1.0f / (s2 + 1e-10f);
    for (int i = tid; i < NS; i += 512) {
        float a = att[i] * inv;
        att[i] = a;
        g_attn[b * NS + i] = a;
        if (full) {
            out[OFF_AT + b * NS + i] = a;
            out[OFF_CV + b * NS + i] = cov[b * NS + i] + a;
        }
    }
    __syncthreads();

    // word_context: thread tid handles memory dim m=tid (512 threads == NM)
    {
        float a0 = 0.0f, a1 = 0.0f;
        const float* mbb = MB + (size_t)b * NS * NM + tid;
#pragma unroll 8
        for (int s = 0; s < NS; s += 2) {
            a0 += att[s] * mbb[(size_t)s * NM];
            a1 += att[s + 1] * mbb[(size_t)(s + 1) * NM];
        }
        float a = a0 + a1;
        wcs[tid] = a;
        g_wc[b * NM + tid] = a;
        if (full) out[OFF_WC + b * NM + tid] = a;
    }
    __syncthreads();

    int yb = y[b];
    float ps = 0.0f;
    for (int i = tid; i < NM + NH + NE; i += 512) {
        float xv = (i < NM) ? wcs[i]
                 : (i < NM + NH) ? h1s[i - NM]
                 : emb_W[(size_t)yb * NE + (i - NM - NH)];
        ps += pgen_W[i] * xv;
    }
    red[tid] = ps; __syncthreads();
    for (int o = 256; o > 0; o >>= 1) { if (tid < o) red[tid] += red[tid + o]; __syncthreads(); }
    float p = sigmoidf_(red[0] + pgen_b[0]);
    if (tid == 0) {
        g_pgen[b] = p;
        if (full) out[OFF_PG + b] = p;
    }

    for (int j = tid; j < NH; j += 512) {
        float a0 = vd1_b[j];
        const float4* w = (const float4*)(vd1_W + (size_t)j * (NM + NH));
        const float4* xw = (const float4*)wcs;
        const float4* xh = (const float4*)h1s;
#pragma unroll 8
        for (int k = 0; k < NM / 4; k++) {
            float4 ww = w[k]; float4 xx = xw[k];
            a0 += ww.x * xx.x + ww.y * xx.y + ww.z * xx.z + ww.w * xx.w;
        }
        const float4* w2 = w + NM / 4;
#pragma unroll 8
        for (int k = 0; k < NH / 4; k++) {
            float4 ww = w2[k]; float4 xx = xh[k];
            a0 += ww.x * xx.x + ww.y * xx.y + ww.z * xx.z + ww.w * xx.w;
        }
        g_hid[b * NH + j] = a0;
    }
}

// ---------------------------------------------------------------------------
// K4a: vocab logits GEMM (tf32 mma): C[64,50000] = hid[64,512] @ vd2_W^T + b2
// BM=64, BN=128, BK=16; 256 thr = 8 warps (2m x 4n); warp tile 32x32.
// grid = ceil(50000/128) = 391
// ---------------------------------------------------------------------------
__global__ __launch_bounds__(256, 1)
void k4a_logits(const float* __restrict__ W2, const float* __restrict__ b2)
{
    __shared__ unsigned As[64 * LDK];
    __shared__ unsigned Bs[128 * LDK];

    int tid = threadIdx.x;
    int wid = tid >> 5, lane = tid & 31;
    int g = lane >> 2, tig = lane & 3;
    int warp_m = wid & 1, warp_n = wid >> 1;
    int vBase = blockIdx.x * 128;

    float acc[2][4][4];
#pragma unroll
    for (int i = 0; i < 2; i++)
#pragma unroll
        for (int j = 0; j < 4; j++)
#pragma unroll
            for (int q = 0; q < 4; q++) acc[i][j][q] = 0.0f;

    int lr = tid >> 2, lc = (tid & 3) * 4;

    for (int k0 = 0; k0 < NH; k0 += 16) {
        {
            float4 a4 = *(const float4*)&g_hid[(size_t)lr * NH + k0 + lc];
            *(uint4*)&As[lr * LDK + lc] =
                make_uint4(f2tf(a4.x), f2tf(a4.y), f2tf(a4.z), f2tf(a4.w));
        }
#pragma unroll
        for (int it = 0; it < 2; it++) {
            int r = lr + it * 64;
            int vr = vBase + r;
            uint4 bv4 = make_uint4(0u, 0u, 0u, 0u);
            if (vr < NV) {
                float4 b4 = *(const float4*)&W2[(size_t)vr * NH + k0 + lc];
                bv4 = make_uint4(f2tf(b4.x), f2tf(b4.y), f2tf(b4.z), f2tf(b4.w));
            }
            *(uint4*)&Bs[r * LDK + lc] = bv4;
        }
        __syncthreads();

#pragma unroll
        for (int ks = 0; ks < 2; ks++) {
            int kb = ks * 8;
            unsigned bf[4][2];
#pragma unroll
            for (int j = 0; j < 4; j++) {
                int col = warp_n * 32 + j * 8 + g;
                bf[j][0] = Bs[col * LDK + kb + tig];
                bf[j][1] = Bs[col * LDK + kb + tig + 4];
            }
#pragma unroll
            for (int i = 0; i < 2; i++) {
                int row = warp_m * 32 + i * 16 + g;
                unsigned a0 = As[row * LDK + kb + tig];
                unsigned a1 = As[(row + 8) * LDK + kb + tig];
                unsigned a2 = As[row * LDK + kb + tig + 4];
                unsigned a3 = As[(row + 8) * LDK + kb + tig + 4];
#pragma unroll
                for (int j = 0; j < 4; j++)
                    mma_tf32(acc[i][j], a0, a1, a2, a3, bf[j][0], bf[j][1]);
            }
        }
        __syncthreads();
    }

#pragma unroll
    for (int i = 0; i < 2; i++) {
        int bb = warp_m * 32 + i * 16 + g;
#pragma unroll
        for (int j = 0; j < 4; j++) {
            int v = vBase + warp_n * 32 + j * 8 + 2 * tig;
            if (v < NV) {
                g_logits[(size_t)bb * NV + v]       = acc[i][j][0] + b2[v];
                g_logits[(size_t)bb * NV + v + 1]   = acc[i][j][1] + b2[v + 1];
                g_logits[(size_t)(bb + 8) * NV + v]     = acc[i][j][2] + b2[v];
                g_logits[(size_t)(bb + 8) * NV + v + 1] = acc[i][j][3] + b2[v + 1];
            }
        }
    }
}

// ---------------------------------------------------------------------------
// K4b: vocab softmax, pointer-generator merge, OOV scatter.
// ---------------------------------------------------------------------------
__global__ void k4b_final(const int* __restrict__ src_oov, float* __restrict__ out)
{
    int b = blockIdx.x, tid = threadIdx.x;
    __shared__ float red[1024];
    const float* lg = &g_logits[(size_t)b * NV];

    float mx = -1e30f;
    for (int v = tid; v < NV; v += 1024) mx = fmaxf(mx, lg[v]);
    red[tid] = mx; __syncthreads();
    for (int o = 512; o > 0; o >>= 1) { if (tid < o) red[tid] = fmaxf(red[tid], red[tid + o]); __syncthreads(); }
    mx = red[0]; __syncthreads();

    float sm = 0.0f;
    for (int v = tid; v < NV; v += 1024) sm += expf(lg[v] - mx);
    red[tid] = sm; __syncthreads();
    for (int o = 512; o > 0; o >>= 1) { if (tid < o) red[tid] += red[tid + o]; __syncthreads(); }
    sm = red[0]; __syncthreads();

    float p = g_pgen[b];
    float scale = p / sm;
    float* orow = out + (size_t)b * NVO;
    for (int v = tid; v < NV; v += 1024) orow[v] = expf(lg[v] - mx) * scale;
    for (int v = NV + tid; v < NVO; v += 1024) orow[v] = 0.0f;
    __syncthreads();

    float q = 1.0f - p;
    for (int s = tid; s < NS; s += 1024) {
        atomicAdd(&orow[src_oov[b * NS + s]], q * g_attn[b * NS + s]);
    }
}

// ---------------------------------------------------------------------------
extern "C" void kernel_launch(void* const* d_in, const int* in_sizes, int n_in,
                              void* d_out, int out_size)
{
    int sh = (n_in >= 23) ? 1 : 0;
    const int*   y        = (const int*)  d_in[0];
    const float* h0g      = (const float*)d_in[1];
    const float* MB       = (const float*)d_in[2];
    const float* mask     = (const float*)d_in[3];
    const int*   src_oov  = (const int*)  d_in[4 + sh];
    const float* cov      = (const float*)d_in[5 + sh];
    const float* emb_W    = (const float*)d_in[6 + sh];
    const float* Wih      = (const float*)d_in[7 + sh];
    const float* Whh      = (const float*)d_in[8 + sh];
    const float* bih      = (const float*)d_in[9 + sh];
    const float* bhh      = (const float*)d_in[10 + sh];
    const float* Wm       = (const float*)d_in[11 + sh];
    const float* Wd       = (const float*)d_in[12 + sh];
    const float* bd       = (const float*)d_in[13 + sh];
    const float* Wc       = (const float*)d_in[14 + sh];
    const float* av       = (const float*)d_in[15 + sh];
    const float* pgen_W   = (const float*)d_in[16 + sh];
    const float* pgen_b   = (const float*)d_in[17 + sh];
    const float* vd1_W    = (const float*)d_in[18 + sh];
    const float* vd1_b    = (const float*)d_in[19 + sh];
    const float* W2       = (const float*)d_in[20 + sh];
    const float* b2       = (const float*)d_in[21 + sh];
    float* out = (float*)d_out;

    k1_gru<<<NB, 256>>>(y, h0g, emb_W, Wih, Whh, bih, bhh, Wd, bd, out, out_size);

    dim3 g2((NB * NS) / 128, NM / 128);   // (200, 4)
    k2_scores<<<g2, 256>>>(MB, Wm, Wc, av, cov);

    k3_attn<<<NB, 512>>>(MB, mask, cov, y, emb_W, pgen_W, pgen_b, vd1_W, vd1_b, out, out_size);

    k4a_logits<<<(NV + 127) / 128, 256>>>(W2, b2);

    k4b_final<<<NB, 1024>>>(src_oov, out);
}

// round 3
// speedup vs baseline: 2.7187x; 1.9154x over previous
#include <cuda_runtime.h>
#include <math.h>

// Problem constants
#define NB 64
#define NS 400
#define NV 50000
#define NE 128
#define NH 512
#define NM 512
#define NOOV 20
#define NVO (NV + NOOV)

// Output layout (flattened concatenation of reference outputs)
#define SZ_FD   (NB * NVO)
#define OFF_H   (SZ_FD)
#define OFF_WC  (OFF_H  + NB * NH)
#define OFF_AT  (OFF_WC + NB * NM)
#define OFF_PG  (OFF_AT + NB * NS)
#define OFF_CV  (OFF_PG + NB)
#define TOTAL_OUT (OFF_CV + NB * NS)

// Scratch (device globals)
__device__ float g_emb[NB * NE];
__device__ float g_gi[NB * 3 * NH];
__device__ float g_gh[NB * 3 * NH];
__device__ float g_h1[NB * NH];
__device__ float g_dec[NB * NH];
__device__ float g_scores[NB * NS];
__device__ float g_attn[NB * NS];
__device__ float g_cat[NB * (NM + NH)];   // [wc | h1]
__device__ float g_hid[NB * NH];
__device__ float g_pgen[NB];
__device__ float g_sumexp[NB];
__device__ float g_logits[(size_t)NB * NV];   // holds exp(logit)

__device__ __forceinline__ float sigmoidf_(float x) { return 1.0f / (1.0f + expf(-x)); }

__device__ __forceinline__ unsigned f2tf(float x) {
    unsigned r; asm("cvt.rna.tf32.f32 %0, %1;" : "=r"(r) : "f"(x)); return r;
}
__device__ __forceinline__ void mma_tf32(float c[4], unsigned a0, unsigned a1,
                                         unsigned a2, unsigned a3,
                                         unsigned b0, unsigned b1) {
    asm volatile("mma.sync.aligned.m16n8k8.row.col.f32.tf32.tf32.f32 "
                 "{%0,%1,%2,%3}, {%4,%5,%6,%7}, {%8,%9}, {%0,%1,%2,%3};"
                 : "+f"(c[0]), "+f"(c[1]), "+f"(c[2]), "+f"(c[3])
                 : "r"(a0), "r"(a1), "r"(a2), "r"(a3), "r"(b0), "r"(b1));
}
__device__ __forceinline__ void cpa16(float* s, const float* g) {
    unsigned sa = (unsigned)__cvta_generic_to_shared(s);
    asm volatile("cp.async.cg.shared.global [%0], [%1], 16;" :: "r"(sa), "l"(g));
}
__device__ __forceinline__ void cpa16p(float* s, const float* g, bool ok) {
    unsigned sa = (unsigned)__cvta_generic_to_shared(s);
    int sz = ok ? 16 : 0;
    asm volatile("cp.async.cg.shared.global [%0], [%1], 16, %2;" :: "r"(sa), "l"(g), "r"(sz));
}
#define CP_COMMIT() asm volatile("cp.async.commit_group;")
#define CP_WAIT1()  asm volatile("cp.async.wait_group 1;")
#define CP_WAIT0()  asm volatile("cp.async.wait_group 0;")

// ---------------------------------------------------------------------------
// K0: gather embedding rows, zero score/sumexp scratch
// ---------------------------------------------------------------------------
__global__ void k0_init(const int* __restrict__ y, const float* __restrict__ emb_W)
{
    int b = blockIdx.x, tid = threadIdx.x;
    int yb = y[b];
    for (int i = tid; i < NE; i += 256) g_emb[b * NE + i] = emb_W[(size_t)yb * NE + i];
    for (int i = tid; i < NS; i += 256) g_scores[b * NS + i] = 0.0f;
    if (b == 0 && tid < NB) g_sumexp[tid] = 0.0f;
}

// ---------------------------------------------------------------------------
// Generic small GEMM: C[64, N] = X[64, K] @ W[N, K]^T + bias, tf32 mma.
// BM=64, BN=64, BK=32; 256 thr = 8 warps (2m x 4n); warp tile 32x16.
// grid.x = N/64. K in {128, 512, 1024}.
// ---------------------------------------------------------------------------
#define GLD 36
template<int K>
__global__ __launch_bounds__(256, 1)
void gemm_nt(const float* __restrict__ X, const float* __restrict__ W,
             const float* __restrict__ bias, float* __restrict__ C, int N)
{
    __shared__ float Xs[2][64 * GLD];
    __shared__ float Ws[2][64 * GLD];
    int tid = threadIdx.x, wid = tid >> 5, lane = tid & 31;
    int g = lane >> 2, tig = lane & 3;
    int warp_m = wid & 1, warp_n = wid >> 1;
    int nBase = blockIdx.x * 64;

    float acc[2][2][4];
#pragma unroll
    for (int i = 0; i < 2; i++)
#pragma unroll
        for (int j = 0; j < 2; j++)
#pragma unroll
            for (int q = 0; q < 4; q++) acc[i][j][q] = 0.0f;

    auto load = [&](int s, int k0) {
#pragma unroll
        for (int it = 0; it < 2; it++) {
            int c = tid + it * 256;
            int row = c >> 3, c4 = (c & 7) * 4;
            cpa16(&Xs[s][row * GLD + c4], &X[(size_t)row * K + k0 + c4]);
            cpa16(&Ws[s][row * GLD + c4], &W[(size_t)(nBase + row) * K + k0 + c4]);
        }
    };

    const int NT = K / 32;
    load(0, 0); CP_COMMIT();
    for (int t = 0; t < NT; t++) {
        if (t + 1 < NT) { load((t + 1) & 1, (t + 1) * 32); CP_COMMIT(); CP_WAIT1(); }
        else CP_WAIT0();
        __syncthreads();
        int s = t & 1;
#pragma unroll
        for (int ks = 0; ks < 4; ks++) {
            int kb = ks * 8;
            unsigned bf[2][2];
#pragma unroll
            for (int j = 0; j < 2; j++) {
                int col = warp_n * 16 + j * 8 + g;
                bf[j][0] = f2tf(Ws[s][col * GLD + kb + tig]);
                bf[j][1] = f2tf(Ws[s][col * GLD + kb + tig + 4]);
            }
#pragma unroll
            for (int i = 0; i < 2; i++) {
                int row = warp_m * 32 + i * 16 + g;
                unsigned a0 = f2tf(Xs[s][row * GLD + kb + tig]);
                unsigned a1 = f2tf(Xs[s][(row + 8) * GLD + kb + tig]);
                unsigned a2 = f2tf(Xs[s][row * GLD + kb + tig + 4]);
                unsigned a3 = f2tf(Xs[s][(row + 8) * GLD + kb + tig + 4]);
#pragma unroll
                for (int j = 0; j < 2; j++)
                    mma_tf32(acc[i][j], a0, a1, a2, a3, bf[j][0], bf[j][1]);
            }
        }
        __syncthreads();
    }

#pragma unroll
    for (int i = 0; i < 2; i++) {
        int bb = warp_m * 32 + i * 16 + g;
#pragma unroll
        for (int j = 0; j < 2; j++) {
            int v = nBase + warp_n * 16 + j * 8 + 2 * tig;
            C[(size_t)bb * N + v]           = acc[i][j][0] + bias[v];
            C[(size_t)bb * N + v + 1]       = acc[i][j][1] + bias[v + 1];
            C[(size_t)(bb + 8) * N + v]     = acc[i][j][2] + bias[v];
            C[(size_t)(bb + 8) * N + v + 1] = acc[i][j][3] + bias[v + 1];
        }
    }
}

// ---------------------------------------------------------------------------
// K1b: GRU gate combine (elementwise). grid=64, 512 thr.
// ---------------------------------------------------------------------------
__global__ void k1b_combine(const float* __restrict__ h0g, float* __restrict__ out,
                            int out_size)
{
    int b = blockIdx.x, j = threadIdx.x;
    float gir = g_gi[b * 3 * NH + j];
    float giz = g_gi[b * 3 * NH + NH + j];
    float gin = g_gi[b * 3 * NH + 2 * NH + j];
    float ghr = g_gh[b * 3 * NH + j];
    float ghz = g_gh[b * 3 * NH + NH + j];
    float ghn = g_gh[b * 3 * NH + 2 * NH + j];
    float h0 = h0g[b * NH + j];
    float r = sigmoidf_(gir + ghr);
    float z = sigmoidf_(giz + ghz);
    float n = tanhf(gin + r * ghn);
    float hv = (1.0f - z) * n + z * h0;
    g_h1[b * NH + j] = hv;
    g_cat[b * (NM + NH) + NM + j] = hv;
    if (out_size >= TOTAL_OUT) out[OFF_H + b * NH + j] = hv;
}

// ---------------------------------------------------------------------------
// K2: enc_feat GEMM (tf32 mma, cp.async 2-stage) + fused score epilogue.
// BM=128, BN=128, BK=16; 256 thr (4m x 2n warps); grid (200, 4)
// ---------------------------------------------------------------------------
#define LDK 20

__global__ __launch_bounds__(256, 1)
void k2_scores(const float* __restrict__ MB, const float* __restrict__ Wm,
               const float* __restrict__ Wc, const float* __restrict__ av,
               const float* __restrict__ cov)
{
    __shared__ float As[2][128 * LDK];
    __shared__ float Bs[2][128 * LDK];
    __shared__ float ssum[128];

    int tid = threadIdx.x;
    int wid = tid >> 5, lane = tid & 31;
    int g = lane >> 2, tig = lane & 3;
    int warp_m = wid & 3, warp_n = wid >> 2;
    int mBase = blockIdx.x * 128;
    int nBase = blockIdx.y * 128;

    float acc[2][8][4];
#pragma unroll
    for (int i = 0; i < 2; i++)
#pragma unroll
        for (int j = 0; j < 8; j++)
#pragma unroll
            for (int q = 0; q < 4; q++) acc[i][j][q] = 0.0f;

    auto load = [&](int s, int k0) {
#pragma unroll
        for (int it = 0; it < 2; it++) {
            int c = tid + it * 256;
            int row = c >> 2, c4 = (c & 3) * 4;
            cpa16(&As[s][row * LDK + c4], &MB[(size_t)(mBase + row) * NM + k0 + c4]);
            cpa16(&Bs[s][row * LDK + c4], &Wm[(size_t)(nBase + row) * NM + k0 + c4]);
        }
    };

    const int NT = NM / 16;   // 32
    load(0, 0); CP_COMMIT();
    for (int t = 0; t < NT; t++) {
        if (t + 1 < NT) { load((t + 1) & 1, (t + 1) * 16); CP_COMMIT(); CP_WAIT1(); }
        else CP_WAIT0();
        __syncthreads();
        int s = t & 1;
#pragma unroll
        for (int ks = 0; ks < 2; ks++) {
            int kb = ks * 8;
            unsigned bf[8][2];
#pragma unroll
            for (int j = 0; j < 8; j++) {
                int col = warp_n * 64 + j * 8 + g;
                bf[j][0] = f2tf(Bs[s][col * LDK + kb + tig]);
                bf[j][1] = f2tf(Bs[s][col * LDK + kb + tig + 4]);
            }
#pragma unroll
            for (int i = 0; i < 2; i++) {
                int row = warp_m * 32 + i * 16 + g;
                unsigned a0 = f2tf(As[s][row * LDK + kb + tig]);
                unsigned a1 = f2tf(As[s][(row + 8) * LDK + kb + tig]);
                unsigned a2 = f2tf(As[s][row * LDK + kb + tig + 4]);
                unsigned a3 = f2tf(As[s][(row + 8) * LDK + kb + tig + 4]);
#pragma unroll
                for (int j = 0; j < 8; j++)
                    mma_tf32(acc[i][j], a0, a1, a2, a3, bf[j][0], bf[j][1]);
            }
        }
        __syncthreads();
    }

    for (int i = tid; i < 128; i += 256) ssum[i] = 0.0f;
    __syncthreads();

#pragma unroll
    for (int i = 0; i < 2; i++) {
#pragma unroll
        for (int h = 0; h < 2; h++) {
            int r = warp_m * 32 + i * 16 + g + h * 8;
            int gr = mBase + r;
            int b = gr / NS;
            int s = gr - b * NS;
            float cv = cov[b * NS + s];
            float partial = 0.0f;
#pragma unroll
            for (int j = 0; j < 8; j++) {
                int hc = nBase + warp_n * 64 + j * 8 + 2 * tig;
                float c0 = acc[i][j][h * 2 + 0];
                float c1 = acc[i][j][h * 2 + 1];
                partial += av[hc]     * tanhf(c0 + g_dec[b * NH + hc]     + cv * Wc[hc]);
                partial += av[hc + 1] * tanhf(c1 + g_dec[b * NH + hc + 1] + cv * Wc[hc + 1]);
            }
            atomicAdd(&ssum[r], partial);
        }
    }
    __syncthreads();
    for (int r = tid; r < 128; r += 256) {
        atomicAdd(&g_scores[mBase + r], ssum[r]);
    }
}

// ---------------------------------------------------------------------------
// K3: masked softmax, coverage, word_context, p_gen. grid=64, 512 thr.
// ---------------------------------------------------------------------------
__global__ void k3_attn(const float* __restrict__ MB, const float* __restrict__ mask,
                        const float* __restrict__ cov,
                        const int* __restrict__ y, const float* __restrict__ emb_W,
                        const float* __restrict__ pgen_W, const float* __restrict__ pgen_b,
                        float* __restrict__ out, int out_size)
{
    int b = blockIdx.x, tid = threadIdx.x;
    bool full = (out_size >= TOTAL_OUT);
    __shared__ float sc[NS];
    __shared__ float att[NS];
    __shared__ float red[512];
    __shared__ float wcs[NM];

    for (int i = tid; i < NS; i += 512) {
        float m = mask[b * NS + i];
        sc[i] = (m > 0.0f) ? g_scores[b * NS + i] : -1e9f;
    }
    __syncthreads();

    float mx = -1e30f;
    for (int i = tid; i < NS; i += 512) mx = fmaxf(mx, sc[i]);
    red[tid] = mx; __syncthreads();
    for (int o = 256; o > 0; o >>= 1) { if (tid < o) red[tid] = fmaxf(red[tid], red[tid + o]); __syncthreads(); }
    mx = red[0]; __syncthreads();

    float sm = 0.0f;
    for (int i = tid; i < NS; i += 512) { float e = expf(sc[i] - mx); sc[i] = e; sm += e; }
    red[tid] = sm; __syncthreads();
    for (int o = 256; o > 0; o >>= 1) { if (tid < o) red[tid] += red[tid + o]; __syncthreads(); }
    sm = red[0]; __syncthreads();

    float s2 = 0.0f;
    for (int i = tid; i < NS; i += 512) {
        float m = mask[b * NS + i];
        float a = sc[i] / sm * m;
        att[i] = a; s2 += a;
    }
    red[tid] = s2; __syncthreads();
    for (int o = 256; o > 0; o >>= 1) { if (tid < o) red[tid] += red[tid + o]; __syncthreads(); }
    s2 = red[0]; __syncthreads();
    float inv = 1.0f / (s2 + 1e-10f);
    for (int i = tid; i < NS; i += 512) {
        float a = att[i] * inv;
        att[i] = a;
        g_attn[b * NS + i] = a;
        if (full) {
            out[OFF_AT + b * NS + i] = a;
            out[OFF_CV + b * NS + i] = cov[b * NS + i] + a;
        }
    }
    __syncthreads();

    // word_context: thread tid -> memory dim tid (512 == NM)
    {
        float a0 = 0.f, a1 = 0.f, a2 = 0.f, a3 = 0.f;
        const float* mbb = MB + (size_t)b * NS * NM + tid;
#pragma unroll 4
        for (int s = 0; s < NS; s += 4) {
            a0 += att[s]     * mbb[(size_t)s * NM];
            a1 += att[s + 1] * mbb[(size_t)(s + 1) * NM];
            a2 += att[s + 2] * mbb[(size_t)(s + 2) * NM];
            a3 += att[s + 3] * mbb[(size_t)(s + 3) * NM];
        }
        float a = (a0 + a1) + (a2 + a3);
        wcs[tid] = a;
        g_cat[b * (NM + NH) + tid] = a;
        if (full) out[OFF_WC + b * NM + tid] = a;
    }
    __syncthreads();

    int yb = y[b];
    float ps = 0.0f;
    for (int i = tid; i < NM + NH + NE; i += 512) {
        float xv = (i < NM) ? wcs[i]
                 : (i < NM + NH) ? g_h1[b * NH + (i - NM)]
                 : emb_W[(size_t)yb * NE + (i - NM - NH)];
        ps += pgen_W[i] * xv;
    }
    red[tid] = ps; __syncthreads();
    for (int o = 256; o > 0; o >>= 1) { if (tid < o) red[tid] += red[tid + o]; __syncthreads(); }
    if (tid == 0) {
        float p = sigmoidf_(red[0] + pgen_b[0]);
        g_pgen[b] = p;
        if (full) out[OFF_PG + b] = p;
    }
}

// ---------------------------------------------------------------------------
// K4a: vocab logits GEMM (tf32 mma, cp.async 2-stage), fused exp + per-b sums.
// C[64,50000] = hid @ vd2_W^T + b2 ; g_logits = exp(C); g_sumexp[b] += sums
// BM=64, BN=128, BK=16; 256 thr (2m x 4n warps); grid 391.
// ---------------------------------------------------------------------------
__global__ __launch_bounds__(256, 1)
void k4a_logits(const float* __restrict__ W2, const float* __restrict__ b2)
{
    __shared__ float As[2][64 * LDK];
    __shared__ float Bs[2][128 * LDK];
    __shared__ float ssum[64];

    int tid = threadIdx.x;
    int wid = tid >> 5, lane = tid & 31;
    int g = lane >> 2, tig = lane & 3;
    int warp_m = wid & 1, warp_n = wid >> 1;
    int vBase = blockIdx.x * 128;

    float acc[2][4][4];
#pragma unroll
    for (int i = 0; i < 2; i++)
#pragma unroll
        for (int j = 0; j < 4; j++)
#pragma unroll
            for (int q = 0; q < 4; q++) acc[i][j][q] = 0.0f;

    auto load = [&](int s, int k0) {
        {   // A: 64x16 = 256 chunks, one per thread
            int row = tid >> 2, c4 = (tid & 3) * 4;
            cpa16(&As[s][row * LDK + c4], &g_hid[(size_t)row * NH + k0 + c4]);
        }
#pragma unroll
        for (int it = 0; it < 2; it++) {   // B: 128x16 = 512 chunks
            int c = tid + it * 256;
            int row = c >> 2, c4 = (c & 3) * 4;
            int vr = vBase + row;
            cpa16p(&Bs[s][row * LDK + c4], &W2[(size_t)vr * NH + k0 + c4], vr < NV);
        }
    };

    const int NT = NH / 16;   // 32
    load(0, 0); CP_COMMIT();
    for (int t = 0; t < NT; t++) {
        if (t + 1 < NT) { load((t + 1) & 1, (t + 1) * 16); CP_COMMIT(); CP_WAIT1(); }
        else CP_WAIT0();
        __syncthreads();
        int s = t & 1;
#pragma unroll
        for (int ks = 0; ks < 2; ks++) {
            int kb = ks * 8;
            unsigned bf[4][2];
#pragma unroll
            for (int j = 0; j < 4; j++) {
                int col = warp_n * 32 + j * 8 + g;
                bf[j][0] = f2tf(Bs[s][col * LDK + kb + tig]);
                bf[j][1] = f2tf(Bs[s][col * LDK + kb + tig + 4]);
            }
#pragma unroll
            for (int i = 0; i < 2; i++) {
                int row = warp_m * 32 + i * 16 + g;
                unsigned a0 = f2tf(As[s][row * LDK + kb + tig]);
                unsigned a1 = f2tf(As[s][(row + 8) * LDK + kb + tig]);
                unsigned a2 = f2tf(As[s][row * LDK + kb + tig + 4]);
                unsigned a3 = f2tf(As[s][(row + 8) * LDK + kb + tig + 4]);
#pragma unroll
                for (int j = 0; j < 4; j++)
                    mma_tf32(acc[i][j], a0, a1, a2, a3, bf[j][0], bf[j][1]);
            }
        }
        __syncthreads();
    }

    if (tid < 64) ssum[tid] = 0.0f;
    __syncthreads();

#pragma unroll
    for (int i = 0; i < 2; i++) {
        int bb = warp_m * 32 + i * 16 + g;
        float rs0 = 0.0f, rs1 = 0.0f;
#pragma unroll
        for (int j = 0; j < 4; j++) {
            int v = vBase + warp_n * 32 + j * 8 + 2 * tig;
            if (v < NV) {
                float e0 = expf(acc[i][j][0] + b2[v]);
                float e1 = expf(acc[i][j][1] + b2[v + 1]);
                float e2 = expf(acc[i][j][2] + b2[v]);
                float e3 = expf(acc[i][j][3] + b2[v + 1]);
                g_logits[(size_t)bb * NV + v]           = e0;
                g_logits[(size_t)bb * NV + v + 1]       = e1;
                g_logits[(size_t)(bb + 8) * NV + v]     = e2;
                g_logits[(size_t)(bb + 8) * NV + v + 1] = e3;
                rs0 += e0 + e1;
                rs1 += e2 + e3;
            }
        }
        atomicAdd(&ssum[bb], rs0);
        atomicAdd(&ssum[bb + 8], rs1);
    }
    __syncthreads();
    if (tid < 64) atomicAdd(&g_sumexp[tid], ssum[tid]);
}

// ---------------------------------------------------------------------------
// K4b: normalize + write final vocab part. grid=(64, 8), 256 thr.
// ---------------------------------------------------------------------------
#define VCHUNK 6250
__global__ void k4b_norm(float* __restrict__ out)
{
    int b = blockIdx.x, ch = blockIdx.y, tid = threadIdx.x;
    float scale = g_pgen[b] / g_sumexp[b];
    const float* lg = &g_logits[(size_t)b * NV];
    float* orow = out + (size_t)b * NVO;
    int v0 = ch * VCHUNK;
    for (int v = v0 + tid; v < v0 + VCHUNK; v += 256) orow[v] = lg[v] * scale;
    if (ch == 0) {
        for (int v = NV + tid; v < NVO; v += 256) orow[v] = 0.0f;
    }
}

// ---------------------------------------------------------------------------
// K4c: OOV pointer scatter. grid=64, 400 thr. (after K4b for ordering)
// ---------------------------------------------------------------------------
__global__ void k4c_scatter(const int* __restrict__ src_oov, float* __restrict__ out)
{
    int b = blockIdx.x, s = threadIdx.x;
    float q = 1.0f - g_pgen[b];
    float* orow = out + (size_t)b * NVO;
    atomicAdd(&orow[src_oov[b * NS + s]], q * g_attn[b * NS + s]);
}

// ---------------------------------------------------------------------------
extern "C" void kernel_launch(void* const* d_in, const int* in_sizes, int n_in,
                              void* d_out, int out_size)
{
    int sh = (n_in >= 23) ? 1 : 0;
    const int*   y        = (const int*)  d_in[0];
    const float* h0g      = (const float*)d_in[1];
    const float* MB       = (const float*)d_in[2];
    const float* mask     = (const float*)d_in[3];
    const int*   src_oov  = (const int*)  d_in[4 + sh];
    const float* cov      = (const float*)d_in[5 + sh];
    const float* emb_W    = (const float*)d_in[6 + sh];
    const float* Wih      = (const float*)d_in[7 + sh];
    const float* Whh      = (const float*)d_in[8 + sh];
    const float* bih      = (const float*)d_in[9 + sh];
    const float* bhh      = (const float*)d_in[10 + sh];
    const float* Wm       = (const float*)d_in[11 + sh];
    const float* Wd       = (const float*)d_in[12 + sh];
    const float* bd       = (const float*)d_in[13 + sh];
    const float* Wc       = (const float*)d_in[14 + sh];
    const float* av       = (const float*)d_in[15 + sh];
    const float* pgen_W   = (const float*)d_in[16 + sh];
    const float* pgen_b   = (const float*)d_in[17 + sh];
    const float* vd1_W    = (const float*)d_in[18 + sh];
    const float* vd1_b    = (const float*)d_in[19 + sh];
    const float* W2       = (const float*)d_in[20 + sh];
    const float* b2       = (const float*)d_in[21 + sh];
    float* out = (float*)d_out;

    float *p_emb, *p_gi, *p_gh, *p_h1, *p_dec, *p_cat, *p_hid;
    cudaGetSymbolAddress((void**)&p_emb, g_emb);
    cudaGetSymbolAddress((void**)&p_gi,  g_gi);
    cudaGetSymbolAddress((void**)&p_gh,  g_gh);
    cudaGetSymbolAddress((void**)&p_h1,  g_h1);
    cudaGetSymbolAddress((void**)&p_dec, g_dec);
    cudaGetSymbolAddress((void**)&p_cat, g_cat);
    cudaGetSymbolAddress((void**)&p_hid, g_hid);

    k0_init<<<NB, 256>>>(y, emb_W);

    gemm_nt<128><<<3 * NH / 64, 256>>>(p_emb, Wih, bih, p_gi, 3 * NH);   // gi
    gemm_nt<512><<<3 * NH / 64, 256>>>(h0g,   Whh, bhh, p_gh, 3 * NH);   // gh
    k1b_combine<<<NB, 512>>>(h0g, out, out_size);
    gemm_nt<512><<<NH / 64, 256>>>(p_h1, Wd, bd, p_dec, NH);             // dec_feat

    dim3 g2((NB * NS) / 128, NM / 128);   // (200, 4)
    k2_scores<<<g2, 256>>>(MB, Wm, Wc, av, cov);

    k3_attn<<<NB, 512>>>(MB, mask, cov, y, emb_W, pgen_W, pgen_b, out, out_size);

    gemm_nt<1024><<<NH / 64, 256>>>(p_cat, vd1_W, vd1_b, p_hid, NH);     // vd1

    k4a_logits<<<(NV + 127) / 128, 256>>>(W2, b2);

    dim3 g4b(NB, 8);
    k4b_norm<<<g4b, 256>>>(out);
    k4c_scatter<<<NB, NS>>>(src_oov, out);
}